// round 5
// baseline (speedup 1.0000x reference)
#include <cuda_runtime.h>
#include <cuda_bf16.h>
#include <cstdint>

// ---------------------------------------------------------------------------
// Problem constants
// ---------------------------------------------------------------------------
static constexpr int B_  = 4;
static constexpr int C_  = 64;
static constexpr int H_  = 256;
static constexpr int W_  = 512;
static constexpr int HW  = H_ * W_;               // 131072
static constexpr int SW_ = 3 * W_;                // 1536
static constexpr int NIDX = 3 * H_ * 3 * W_;      // 3538944
static constexpr int TILE_P = 128;
static constexpr int TILES_PER_B = HW / TILE_P;   // 1024
static constexpr int N_TILES = B_ * TILES_PER_B;  // 4096
static constexpr int THREADS = 512;               // 16 warps

// A tiles: 128 rows (pixels) x 64 ci, row pitch 68 floats (conflict-free)
static constexpr int A_PITCH = 68;
static constexpr int A_BYTES = TILE_P * A_PITCH * 4;     // 34816
// W: per tap 32 (ks*4+tig) rows x 64 co float2, pitch 68 float2
static constexpr int W_PITCH = 68;                        // in float2 units
static constexpr int W_TAP_F2 = 32 * W_PITCH;             // 2176 float2 per tap
static constexpr int W_BYTES = 9 * W_TAP_F2 * 8;          // 156672

static constexpr int SMEM_BIAS = 0;                       // 256 B
static constexpr int SMEM_W    = 256;                     // 156672 B
static constexpr int SMEM_A0   = 157696;                  // 1024-aligned
static constexpr int SMEM_A1   = SMEM_A0 + A_BYTES;       // 192512
static constexpr int SMEM_TOTAL = SMEM_A1 + A_BYTES;      // 227328
static constexpr int STG_PITCH = 132;                     // output staging pitch

__device__ int   g_idx_is64;
__device__ int   g_idx32[NIDX];
__device__ float g_xt[(size_t)B_ * HW * C_];   // [B][HW][C], tf32-rounded

// ---------------------------------------------------------------------------
// helpers
// ---------------------------------------------------------------------------
__device__ __forceinline__ float to_tf32(float x) {
    uint32_t u;
    asm("cvt.rna.tf32.f32 %0, %1;" : "=r"(u) : "f"(x));
    return __uint_as_float(u);
}

__device__ __forceinline__ void mma_tf32(float* c, const float* a, float b0, float b1) {
    asm volatile(
        "mma.sync.aligned.m16n8k8.row.col.f32.tf32.tf32.f32 "
        "{%0,%1,%2,%3}, {%4,%5,%6,%7}, {%8,%9}, {%0,%1,%2,%3};"
        : "+f"(c[0]), "+f"(c[1]), "+f"(c[2]), "+f"(c[3])
        : "r"(__float_as_uint(a[0])), "r"(__float_as_uint(a[1])),
          "r"(__float_as_uint(a[2])), "r"(__float_as_uint(a[3])),
          "r"(__float_as_uint(b0)),  "r"(__float_as_uint(b1)));
}

// ---------------------------------------------------------------------------
// Kernel 0: detect int64 vs int32 index dtype
// ---------------------------------------------------------------------------
__global__ void detect_kernel(const unsigned int* __restrict__ w) {
    if (threadIdx.x == 0) {
        int is64 = 1;
        for (int i = 0; i < 64; ++i)
            if (w[2 * i + 1] != 0u) { is64 = 0; break; }
        g_idx_is64 = is64;
    }
}

// ---------------------------------------------------------------------------
// Kernel 1: convert idx to int32
// ---------------------------------------------------------------------------
__global__ void idx_convert(const void* __restrict__ idx_raw) {
    int i = blockIdx.x * blockDim.x + threadIdx.x;
    if (i < NIDX) {
        g_idx32[i] = g_idx_is64 ? (int)((const long long*)idx_raw)[i]
                                : ((const int*)idx_raw)[i];
    }
}

// ---------------------------------------------------------------------------
// Kernel 2: transpose x [B][C][HW] -> g_xt [B][HW][C], rounding to tf32
// ---------------------------------------------------------------------------
__global__ void transpose_kernel(const float* __restrict__ x) {
    __shared__ float t[32][33];
    const int b  = blockIdx.z;
    const int cb = blockIdx.y * 32;
    const int gb = blockIdx.x * 32;
    const int tx = threadIdx.x, ty = threadIdx.y;
    const float* xb = x + (size_t)b * C_ * HW;
#pragma unroll
    for (int i = 0; i < 32; i += 8)
        t[ty + i][tx] = xb[(size_t)(cb + ty + i) * HW + gb + tx];
    __syncthreads();
    float* xtb = g_xt + (size_t)b * HW * C_;
#pragma unroll
    for (int i = 0; i < 32; i += 8)
        xtb[(size_t)(gb + ty + i) * C_ + cb + tx] = to_tf32(t[tx][ty + i]);
}

// ---------------------------------------------------------------------------
// Kernel 3: persistent fused gather + 9-tap GEMM via mma.sync tf32
// 512 threads / 16 warps. warp w: pixel block mb = w>>1 (16 px),
// co half ch = w&1 (32 co). Per-warp MMA tile: M=16 x N=32.
// ---------------------------------------------------------------------------
__global__ void __launch_bounds__(THREADS, 1)
latconv_main(const float* __restrict__ wgt,
             const float* __restrict__ bias,
             float* __restrict__ out) {
    extern __shared__ char smem[];
    float*  bsm = (float*)(smem + SMEM_BIAS);
    float*  wsm = (float*)(smem + SMEM_W);

    const int tid = threadIdx.x;
    const int wid = tid >> 5;
    const int lid = tid & 31;
    const int gid = lid >> 2;      // 0..7
    const int tig = lid & 3;       // 0..3
    const int mb  = wid >> 1;      // 0..7  pixel block (16 px)
    const int ch  = wid & 1;       // 0..1  co half (32 co)

    if (tid < C_) bsm[tid] = bias[tid];

    // Stage all weights once: pair layout [tap][ks*4+tig][co].{ci, ci+4}
    for (int e = tid; e < C_ * C_ * 9; e += THREADS) {
        int co  = e / (C_ * 9);
        int r   = e - co * C_ * 9;
        int ci  = r / 9;
        int j   = r - ci * 9;
        float v = to_tf32(wgt[e]);
        int ks  = ci >> 3;
        int rr  = ci & 7;
        int tg  = rr & 3;
        int cmp = rr >> 2;
        wsm[(j * W_TAP_F2 + (ks * 4 + tg) * W_PITCH + co) * 2 + cmp] = v;
    }
    __syncthreads();

    for (int tile = blockIdx.x; tile < N_TILES; tile += gridDim.x) {
        const int b    = tile >> 10;
        const int pt   = tile & (TILES_PER_B - 1);
        const int hRow = pt >> 2;
        const int wB   = (pt & 3) * TILE_P;
        const float* xtb = g_xt + (size_t)b * HW * C_;

        float acc[4][4];
#pragma unroll
        for (int nt = 0; nt < 4; ++nt)
#pragma unroll
            for (int q = 0; q < 4; ++q) acc[nt][q] = 0.f;

        // gather tap 0 into buf0
        {
            const int rowBase = (hRow * 3 + 0) * SW_ + 0 + 3 * wB;
            float* ab = (float*)(smem + SMEM_A0);
#pragma unroll
            for (int it = 0; it < (TILE_P * 16) / THREADS; ++it) {
                int lin = it * THREADS + tid;
                int p   = lin >> 4;
                int c4  = lin & 15;
                int g   = g_idx32[rowBase + 3 * p];
                float4 v = *(const float4*)(xtb + (size_t)g * C_ + c4 * 4);
                *(float4*)(ab + p * A_PITCH + c4 * 4) = v;
            }
        }
        __syncthreads();

#pragma unroll 1
        for (int j = 0; j < 9; ++j) {
            // prefetch-gather tap j+1 into the other buffer
            if (j < 8) {
                int jn = j + 1;
                int kh = jn / 3, kw = jn - kh * 3;
                const int rowBase = (hRow * 3 + kh) * SW_ + kw + 3 * wB;
                float* ab = (float*)(smem + (((jn & 1) ? SMEM_A1 : SMEM_A0)));
#pragma unroll
                for (int it = 0; it < (TILE_P * 16) / THREADS; ++it) {
                    int lin = it * THREADS + tid;
                    int p   = lin >> 4;
                    int c4  = lin & 15;
                    int g   = g_idx32[rowBase + 3 * p];
                    float4 v = *(const float4*)(xtb + (size_t)g * C_ + c4 * 4);
                    *(float4*)(ab + p * A_PITCH + c4 * 4) = v;
                }
            }

            // compute tap j from buf (j&1); per-warp tile M=16 x N=32
            {
                const float* ab = (const float*)(smem + ((j & 1) ? SMEM_A1 : SMEM_A0));
                const float2* wtap = (const float2*)wsm + j * W_TAP_F2;
#pragma unroll
                for (int ks = 0; ks < 8; ++ks) {
                    float a[4];
                    int base = (mb * 16 + gid) * A_PITCH + ks * 8 + tig;
                    a[0] = ab[base];
                    a[1] = ab[base + 8 * A_PITCH];
                    a[2] = ab[base + 4];
                    a[3] = ab[base + 8 * A_PITCH + 4];
                    const float2* wrow = wtap + (ks * 4 + tig) * W_PITCH + ch * 32;
#pragma unroll
                    for (int nt = 0; nt < 4; ++nt) {
                        float2 bv = wrow[nt * 8 + gid];
                        mma_tf32(acc[nt], a, bv.x, bv.y);
                    }
                }
            }
            __syncthreads();
        }

        // epilogue: stage D transposed [co][px] into buf1 (free after tap 7)
        {
            float* stg = (float*)(smem + SMEM_A1);
            const int p0 = mb * 16 + gid;
#pragma unroll
            for (int nt = 0; nt < 4; ++nt) {
                int c0 = ch * 32 + nt * 8 + 2 * tig;
                float b0 = bsm[c0], b1 = bsm[c0 + 1];
                stg[c0 * STG_PITCH + p0]            = acc[nt][0] + b0;
                stg[(c0 + 1) * STG_PITCH + p0]      = acc[nt][1] + b1;
                stg[c0 * STG_PITCH + p0 + 8]        = acc[nt][2] + b0;
                stg[(c0 + 1) * STG_PITCH + p0 + 8]  = acc[nt][3] + b1;
            }
        }
        __syncthreads();

        // coalesced global store: 512B per co row
        {
            const float* stg = (const float*)(smem + SMEM_A1);
            const size_t obase = (size_t)b * C_ * HW + (size_t)pt * TILE_P;
#pragma unroll
            for (int e = tid; e < C_ * TILE_P; e += THREADS) {
                int c = e >> 7;
                int p = e & (TILE_P - 1);
                out[obase + (size_t)c * HW + p] = stg[c * STG_PITCH + p];
            }
        }
        __syncthreads();   // stg (buf1) must drain before next tile's gathers
    }
}

// ---------------------------------------------------------------------------
// Launch
// ---------------------------------------------------------------------------
extern "C" void kernel_launch(void* const* d_in, const int* in_sizes, int n_in,
                              void* d_out, int out_size) {
    const float* x    = (const float*)d_in[0];
    const void*  idx  = d_in[1];
    const float* wgt  = (const float*)d_in[2];
    const float* bias = (const float*)d_in[3];
    float* out        = (float*)d_out;

    detect_kernel<<<1, 32>>>((const unsigned int*)idx);
    idx_convert<<<(NIDX + 255) / 256, 256>>>(idx);

    dim3 tb(32, 8);
    dim3 tg(HW / 32, C_ / 32, B_);
    transpose_kernel<<<tg, tb>>>(x);

    cudaFuncSetAttribute(latconv_main, cudaFuncAttributeMaxDynamicSharedMemorySize,
                         SMEM_TOTAL);
    int sm_count = 0;
    cudaDeviceGetAttribute(&sm_count, cudaDevAttrMultiProcessorCount, 0);
    if (sm_count <= 0) sm_count = 148;

    latconv_main<<<sm_count, THREADS, SMEM_TOTAL>>>(wgt, bias, out);
}

// round 6
// speedup vs baseline: 1.8589x; 1.8589x over previous
#include <cuda_runtime.h>
#include <cuda_fp16.h>
#include <cstdint>

// ---------------------------------------------------------------------------
// Problem constants
// ---------------------------------------------------------------------------
static constexpr int B_  = 4;
static constexpr int C_  = 64;
static constexpr int H_  = 256;
static constexpr int W_  = 512;
static constexpr int HW  = H_ * W_;               // 131072
static constexpr int SW_ = 3 * W_;                // 1536
static constexpr int NIDX = 3 * H_ * 3 * W_;      // 3538944
static constexpr int TILE_P = 256;                // one half-row of output
static constexpr int TILES_PER_B = HW / TILE_P;   // 512
static constexpr int N_TILES = B_ * TILES_PER_B;  // 2048
static constexpr int THREADS = 512;               // 16 warps

// A ring buffers: 256 px rows x 72 halves (144B pitch; 128B data + 16B pad)
static constexpr int A_PITCH_B = 144;
static constexpr int A_BYTES   = TILE_P * A_PITCH_B;        // 36864
// W: [tap][co][ci] halves, co-row pitch 72 halves (144B)
static constexpr int W_ROW_H   = 72;
static constexpr int W_TAP_H   = C_ * W_ROW_H;              // 4608 halves
static constexpr int W_BYTES   = 9 * W_TAP_H * 2;           // 82944

static constexpr int SMEM_W  = 0;
static constexpr int SMEM_A  = W_BYTES;                     // 82944 (1024-aligned)
static constexpr int SMEM_TOTAL = SMEM_A + 3 * A_BYTES;     // 193536

__device__ int    g_idx_is64;
__device__ int    g_idx32[NIDX];
__device__ __align__(128) __half g_xt[(size_t)B_ * HW * C_];  // [B][HW][C] fp16

// ---------------------------------------------------------------------------
// PTX helpers
// ---------------------------------------------------------------------------
__device__ __forceinline__ uint32_t smem_u32(const void* p) {
    uint32_t a;
    asm("{ .reg .u64 t; cvta.to.shared.u64 t, %1; cvt.u32.u64 %0, t; }" : "=r"(a) : "l"(p));
    return a;
}

__device__ __forceinline__ void ldmatrix_x4(uint32_t* r, uint32_t addr) {
    asm volatile("ldmatrix.sync.aligned.m8n8.x4.shared.b16 {%0,%1,%2,%3}, [%4];"
                 : "=r"(r[0]), "=r"(r[1]), "=r"(r[2]), "=r"(r[3]) : "r"(addr));
}

__device__ __forceinline__ void mma_f16(float* c, const uint32_t* a, uint32_t b0, uint32_t b1) {
    asm volatile(
        "mma.sync.aligned.m16n8k16.row.col.f32.f16.f16.f32 "
        "{%0,%1,%2,%3}, {%4,%5,%6,%7}, {%8,%9}, {%0,%1,%2,%3};"
        : "+f"(c[0]), "+f"(c[1]), "+f"(c[2]), "+f"(c[3])
        : "r"(a[0]), "r"(a[1]), "r"(a[2]), "r"(a[3]), "r"(b0), "r"(b1));
}

#define CP_ASYNC16(dst, src) \
    asm volatile("cp.async.ca.shared.global [%0], [%1], 16;" :: "r"(dst), "l"(src))
#define CP_COMMIT()  asm volatile("cp.async.commit_group;" ::: "memory")
#define CP_WAIT1()   asm volatile("cp.async.wait_group 1;" ::: "memory")

// ---------------------------------------------------------------------------
// Kernel 0/1: idx dtype detect + convert to int32
// ---------------------------------------------------------------------------
__global__ void detect_kernel(const unsigned int* __restrict__ w) {
    if (threadIdx.x == 0) {
        int is64 = 1;
        for (int i = 0; i < 64; ++i)
            if (w[2 * i + 1] != 0u) { is64 = 0; break; }
        g_idx_is64 = is64;
    }
}

__global__ void idx_convert(const void* __restrict__ idx_raw) {
    int i = blockIdx.x * blockDim.x + threadIdx.x;
    if (i < NIDX) {
        g_idx32[i] = g_idx_is64 ? (int)((const long long*)idx_raw)[i]
                                : ((const int*)idx_raw)[i];
    }
}

// ---------------------------------------------------------------------------
// Kernel 2: transpose x [B][C][HW] -> g_xt [B][HW][C] fp16
// ---------------------------------------------------------------------------
__global__ void transpose_kernel(const float* __restrict__ x) {
    __shared__ float t[32][33];
    const int b  = blockIdx.z;
    const int cb = blockIdx.y * 32;
    const int gb = blockIdx.x * 32;
    const int tx = threadIdx.x, ty = threadIdx.y;
    const float* xb = x + (size_t)b * C_ * HW;
#pragma unroll
    for (int i = 0; i < 32; i += 8)
        t[ty + i][tx] = xb[(size_t)(cb + ty + i) * HW + gb + tx];
    __syncthreads();
    __half* xtb = g_xt + ((size_t)b * HW) * C_;
    const int e0 = ty * 32 + tx;     // 0..255
#pragma unroll
    for (int r = 0; r < 2; ++r) {
        int e   = e0 + r * 256;      // 0..511
        int hwl = e >> 4;            // 0..31
        int c2  = e & 15;            // 0..15
        __half2 v = __floats2half2_rn(t[2 * c2][hwl], t[2 * c2 + 1][hwl]);
        *(__half2*)(xtb + (size_t)(gb + hwl) * C_ + cb + 2 * c2) = v;
    }
}

// ---------------------------------------------------------------------------
// Kernel 3: persistent fused gather(cp.async, 3-stage ring) + fp16 MMA
// tile = 256 px x 64 co.  16 warps: mb=wid>>1 (32 px), ch=wid&1 (32 co).
// per warp per tap: 4 ks x (2 ldmatrix.x4 + 4x(2 LDS.32 B) ) + 32 mma.
// ---------------------------------------------------------------------------
struct Cur { int tile; int tap; };
__device__ __forceinline__ void adv(Cur& c, int stride) {
    if (++c.tap == 9) { c.tap = 0; c.tile += stride; }
}

__device__ __forceinline__ int load_idx(const Cur& c, int p) {
    int pt   = c.tile & (TILES_PER_B - 1);
    int hRow = pt >> 1;
    int wB   = (pt & 1) << 8;
    int kh   = c.tap / 3;
    int kw   = c.tap - kh * 3;
    return g_idx32[(3 * hRow + kh) * SW_ + 3 * (wB + p) + kw];
}

__device__ __forceinline__ void issue_gather(int tile, int g, int p, int h,
                                             uint32_t dstbase) {
    int b = tile >> 9;
    const char* src = (const char*)g_xt
                    + (((size_t)b << 17) + (uint32_t)g) * (C_ * 2) + (h << 6);
    uint32_t dst = dstbase + p * A_PITCH_B + (h << 6);
#pragma unroll
    for (int k = 0; k < 4; ++k)
        CP_ASYNC16(dst + k * 16, src + k * 16);
}

__global__ void __launch_bounds__(THREADS, 1)
latconv_main(const float* __restrict__ wgt,
             const float* __restrict__ bias,
             float* __restrict__ out) {
    extern __shared__ char smem[];
    __half* wsm = (__half*)(smem + SMEM_W);

    const int tid = threadIdx.x;
    const int wid = tid >> 5;
    const int lid = tid & 31;
    const int gid = lid >> 2;       // 0..7
    const int tig = lid & 3;        // 0..3
    const int mb  = wid >> 1;       // 0..7 : 32-pixel block
    const int ch  = wid & 1;        // 0..1 : 32-co half

    // gather roles
    const int gp = tid >> 1;        // pixel 0..255
    const int gh = tid & 1;         // half-row 0/1

    // ldmatrix per-lane address constant
    const int lm = lid >> 3, lr = lid & 7;
    const uint32_t lconst = (uint32_t)(((lm & 1) * 8 + lr) * A_PITCH_B
                                       + (lm >> 1) * 16 + mb * 32 * A_PITCH_B);

    // stage weights as fp16: wsm[j][co][ci], e = (j*64+co)*64+ci
    for (int e = tid; e < C_ * C_ * 9; e += THREADS) {
        int ci = e & 63, co = (e >> 6) & 63, j = e >> 12;
        wsm[j * W_TAP_H + co * W_ROW_H + ci] =
            __float2half_rn(wgt[co * 576 + ci * 9 + j]);
    }

    // per-thread bias registers (co mapping is tile-invariant)
    float br[4][2];
#pragma unroll
    for (int nt = 0; nt < 4; ++nt) {
        int co = ch * 32 + nt * 8 + 2 * tig;
        br[nt][0] = bias[co];
        br[nt][1] = bias[co + 1];
    }
    __syncthreads();

    const uint32_t abase0 = smem_u32(smem + SMEM_A);

    // local tile count / flat steps
    int nloc = 0;
    for (int t = blockIdx.x; t < N_TILES; t += gridDim.x) nloc++;
    const int S = nloc * 9;
    if (S == 0) return;

    // prologue: issue steps 0 and 1
    Cur c_iss = {(int)blockIdx.x, 0};
    {
        int g0 = load_idx(c_iss, gp);
        issue_gather(c_iss.tile, g0, gp, gh, abase0 + 0 * A_BYTES);
        CP_COMMIT();
        adv(c_iss, gridDim.x);
        int g1 = load_idx(c_iss, gp);
        issue_gather(c_iss.tile, g1, gp, gh, abase0 + 1 * A_BYTES);
        CP_COMMIT();
        adv(c_iss, gridDim.x);          // c_iss now at step 2
    }
    Cur c_pre = c_iss;                  // prefetch cursor (idx for c_iss's step)
    int r_use = (S > 2) ? load_idx(c_pre, gp) : 0;
    adv(c_pre, gridDim.x);              // c_pre now at step 3

    Cur c_cmp = {(int)blockIdx.x, 0};
    int b_iss = 2, b_cmp = 0;           // ring buffer indices

    float acc[2][4][4];

    for (int s = 0; s < S; ++s) {
        CP_WAIT1();
        __syncthreads();

        if (s + 2 < S) {
            issue_gather(c_iss.tile, r_use, gp, gh, abase0 + b_iss * A_BYTES);
        }
        CP_COMMIT();
        if (s + 3 < S) r_use = load_idx(c_pre, gp);
        adv(c_iss, gridDim.x);
        adv(c_pre, gridDim.x);
        if (++b_iss == 3) b_iss = 0;

        if (c_cmp.tap == 0) {
#pragma unroll
            for (int mh = 0; mh < 2; ++mh)
#pragma unroll
                for (int nt = 0; nt < 4; ++nt)
#pragma unroll
                    for (int q = 0; q < 4; ++q) acc[mh][nt][q] = 0.f;
        }

        // compute tap c_cmp.tap from ring buffer b_cmp
        {
            const uint32_t ab = abase0 + b_cmp * A_BYTES;
            const __half* wt = wsm + c_cmp.tap * W_TAP_H
                             + (ch * 32 + gid) * W_ROW_H + tig * 2;
#pragma unroll
            for (int ks = 0; ks < 4; ++ks) {
                uint32_t a[2][4];
#pragma unroll
                for (int mh = 0; mh < 2; ++mh)
                    ldmatrix_x4(a[mh], ab + lconst + mh * (16 * A_PITCH_B) + ks * 32);
#pragma unroll
                for (int nt = 0; nt < 4; ++nt) {
                    const __half* wp = wt + nt * 8 * W_ROW_H + ks * 16;
                    uint32_t b0 = *(const uint32_t*)(wp);
                    uint32_t b1 = *(const uint32_t*)(wp + 8);
                    mma_f16(acc[0][nt], a[0], b0, b1);
                    mma_f16(acc[1][nt], a[1], b0, b1);
                }
            }
        }

        if (c_cmp.tap == 8) {
            // epilogue: direct STG from accumulators
            int b  = c_cmp.tile >> 9;
            int pt = c_cmp.tile & (TILES_PER_B - 1);
            int hw0 = (pt >> 1) * W_ + ((pt & 1) << 8);
            float* op = out + ((size_t)b << 23) + hw0;
#pragma unroll
            for (int mh = 0; mh < 2; ++mh) {
                int px = mb * 32 + mh * 16 + gid;
#pragma unroll
                for (int nt = 0; nt < 4; ++nt) {
                    int co = ch * 32 + nt * 8 + 2 * tig;
                    float* q = op + (size_t)co * HW + px;
                    q[0]      = acc[mh][nt][0] + br[nt][0];
                    q[HW]     = acc[mh][nt][1] + br[nt][1];
                    q[8]      = acc[mh][nt][2] + br[nt][0];
                    q[HW + 8] = acc[mh][nt][3] + br[nt][1];
                }
            }
        }

        adv(c_cmp, gridDim.x);
        if (++b_cmp == 3) b_cmp = 0;
    }
}

// ---------------------------------------------------------------------------
// Launch
// ---------------------------------------------------------------------------
extern "C" void kernel_launch(void* const* d_in, const int* in_sizes, int n_in,
                              void* d_out, int out_size) {
    const float* x    = (const float*)d_in[0];
    const void*  idx  = d_in[1];
    const float* wgt  = (const float*)d_in[2];
    const float* bias = (const float*)d_in[3];
    float* out        = (float*)d_out;

    detect_kernel<<<1, 32>>>((const unsigned int*)idx);
    idx_convert<<<(NIDX + 255) / 256, 256>>>(idx);

    dim3 tb(32, 8);
    dim3 tg(HW / 32, C_ / 32, B_);
    transpose_kernel<<<tg, tb>>>(x);

    cudaFuncSetAttribute(latconv_main, cudaFuncAttributeMaxDynamicSharedMemorySize,
                         SMEM_TOTAL);
    int sm_count = 0;
    cudaDeviceGetAttribute(&sm_count, cudaDevAttrMultiProcessorCount, 0);
    if (sm_count <= 0) sm_count = 148;

    latconv_main<<<sm_count, THREADS, SMEM_TOTAL>>>(wgt, bias, out);
}

// round 7
// speedup vs baseline: 1.9983x; 1.0750x over previous
#include <cuda_runtime.h>
#include <cuda_fp16.h>
#include <cstdint>

// ---------------------------------------------------------------------------
// Problem constants
// ---------------------------------------------------------------------------
static constexpr int B_  = 4;
static constexpr int C_  = 64;
static constexpr int H_  = 256;
static constexpr int W_  = 512;
static constexpr int HW  = H_ * W_;               // 131072 = 2^17
static constexpr int SW_ = 3 * W_;                // 1536
static constexpr int TILE_P = 256;                // one half-row of output
static constexpr int TILES_PER_B = HW / TILE_P;   // 512
static constexpr int N_TILES = B_ * TILES_PER_B;  // 2048
static constexpr int THREADS = 512;               // 16 warps

// A ring buffers: 256 px rows x 144B pitch (128B data + 16B pad)
static constexpr int A_PITCH_B = 144;
static constexpr int A_BYTES   = TILE_P * A_PITCH_B;        // 36864
static constexpr int A_FILL_B  = TILE_P * 128;              // 32768 tx bytes
// W: [tap][co][ci] halves, co-row pitch 72 halves (144B)
static constexpr int W_ROW_H   = 72;
static constexpr int W_TAP_H   = C_ * W_ROW_H;              // 4608 halves
static constexpr int W_BYTES   = 9 * W_TAP_H * 2;           // 82944

static constexpr int SMEM_W   = 0;
static constexpr int SMEM_BAR = W_BYTES;                    // 3 x 8B mbarriers
static constexpr int SMEM_A   = W_BYTES + 128;              // 83072 (128-aligned)
static constexpr int SMEM_TOTAL = SMEM_A + 3 * A_BYTES;     // 193664

__device__ int    g_idx_is64;
__device__ __align__(128) __half g_xt[(size_t)B_ * HW * C_];  // [B][HW][C] fp16

// ---------------------------------------------------------------------------
// PTX helpers
// ---------------------------------------------------------------------------
__device__ __forceinline__ uint32_t smem_u32(const void* p) {
    uint32_t a;
    asm("{ .reg .u64 t; cvta.to.shared.u64 t, %1; cvt.u32.u64 %0, t; }" : "=r"(a) : "l"(p));
    return a;
}

__device__ __forceinline__ void ldmatrix_x4(uint32_t* r, uint32_t addr) {
    asm volatile("ldmatrix.sync.aligned.m8n8.x4.shared.b16 {%0,%1,%2,%3}, [%4];"
                 : "=r"(r[0]), "=r"(r[1]), "=r"(r[2]), "=r"(r[3]) : "r"(addr));
}

__device__ __forceinline__ void mma_f16(float* c, const uint32_t* a, uint32_t b0, uint32_t b1) {
    asm volatile(
        "mma.sync.aligned.m16n8k16.row.col.f32.f16.f16.f32 "
        "{%0,%1,%2,%3}, {%4,%5,%6,%7}, {%8,%9}, {%0,%1,%2,%3};"
        : "+f"(c[0]), "+f"(c[1]), "+f"(c[2]), "+f"(c[3])
        : "r"(a[0]), "r"(a[1]), "r"(a[2]), "r"(a[3]), "r"(b0), "r"(b1));
}

#define MBARRIER_INIT(bar, cnt) \
    asm volatile("mbarrier.init.shared.b64 [%0], %1;" :: "r"(bar), "r"((uint32_t)(cnt)) : "memory")

#define MBARRIER_EXPECT_TX(bar, bytes) \
    asm volatile("mbarrier.arrive.expect_tx.shared.b64 _, [%0], %1;" \
                 :: "r"(bar), "r"((uint32_t)(bytes)) : "memory")

#define MBARRIER_WAIT_PARITY(bar, ph) do {                                              \
    uint32_t _m = (bar); uint32_t _p = (ph); uint32_t _d;                               \
    asm volatile("{\n\t.reg .pred p;\n\t"                                               \
        "mbarrier.try_wait.parity.acquire.cta.shared::cta.b64 p, [%1], %2;\n\t"         \
        "selp.b32 %0, 1, 0, p;\n\t}" : "=r"(_d) : "r"(_m), "r"(_p) : "memory");         \
    if (!_d) {                                                                          \
        asm volatile("{\n\t.reg .pred P1;\n\t"                                          \
            "WL_%=:\n\t"                                                                \
            "mbarrier.try_wait.parity.acquire.cta.shared::cta.b64 P1, [%0], %1, 0x989680;\n\t" \
            "@P1 bra.uni WD_%=;\n\t"                                                    \
            "bra.uni WL_%=;\n\t"                                                        \
            "WD_%=:\n\t}" :: "r"(_m), "r"(_p) : "memory");                              \
    }                                                                                   \
} while (0)

// one 128-byte row: global -> shared, completion counted on mbar
__device__ __forceinline__ void bulk_row(uint32_t dst, const void* src, uint32_t mbar) {
    asm volatile(
        "cp.async.bulk.shared::cta.global.mbarrier::complete_tx::bytes [%0], [%1], 128, [%2];"
        :: "r"(dst), "l"(src), "r"(mbar) : "memory");
}

// ---------------------------------------------------------------------------
// Kernel 0: idx dtype detect
// ---------------------------------------------------------------------------
__global__ void detect_kernel(const unsigned int* __restrict__ w) {
    if (threadIdx.x == 0) {
        int is64 = 1;
        for (int i = 0; i < 64; ++i)
            if (w[2 * i + 1] != 0u) { is64 = 0; break; }
        g_idx_is64 = is64;
    }
}

// ---------------------------------------------------------------------------
// Kernel 1: transpose x [B][C][HW] -> g_xt [B][HW][C] fp16 (coalesced stores)
// ---------------------------------------------------------------------------
__global__ void transpose_kernel(const float* __restrict__ x) {
    __shared__ float t[32][33];
    const int b  = blockIdx.z;
    const int cb = blockIdx.y * 32;
    const int gb = blockIdx.x * 32;
    const int tx = threadIdx.x, ty = threadIdx.y;
    const float* xb = x + (size_t)b * C_ * HW;
#pragma unroll
    for (int i = 0; i < 32; i += 8)
        t[ty + i][tx] = xb[(size_t)(cb + ty + i) * HW + gb + tx];
    __syncthreads();
    __half* xtb = g_xt + ((size_t)b * HW) * C_;
    const int c2  = tx & 15;       // half2 index within 32-channel slab
    const int sel = tx >> 4;       // 0/1
#pragma unroll
    for (int i = 0; i < 2; ++i) {
        int hwl = ty * 4 + sel * 2 + i;   // 0..31, each exactly once
        __half2 v = __floats2half2_rn(t[2 * c2][hwl], t[2 * c2 + 1][hwl]);
        *(__half2*)(xtb + (size_t)(gb + hwl) * C_ + cb + 2 * c2) = v;
    }
}

// ---------------------------------------------------------------------------
// Kernel 2: persistent fused gather (cp.async.bulk, 3-stage mbarrier ring)
//           + fp16 mma.sync.  tile = 256 px x 64 co.
// ---------------------------------------------------------------------------
struct Cur { int tile; int tap; };
__device__ __forceinline__ void adv(Cur& c, int stride) {
    if (++c.tap == 9) { c.tap = 0; c.tile += stride; }
}

__device__ __forceinline__ int load_idx(const void* idx, int is64, const Cur& c, int p) {
    int pt   = c.tile & (TILES_PER_B - 1);
    int hRow = pt >> 1;
    int wB   = (pt & 1) << 8;
    int kh   = c.tap / 3;
    int kw   = c.tap - kh * 3;
    int o    = (3 * hRow + kh) * SW_ + 3 * (wB + p) + kw;
    return is64 ? (int)((const long long*)idx)[o] : ((const int*)idx)[o];
}

__device__ __forceinline__ void issue_row(int tile, int g, int p,
                                          uint32_t stage_base, uint32_t mbar) {
    const char* src = (const char*)g_xt
                    + ((((size_t)(tile >> 9)) << 17) + (uint32_t)g) * (C_ * 2);
    bulk_row(stage_base + p * A_PITCH_B, src, mbar);
}

__global__ void __launch_bounds__(THREADS, 1)
latconv_main(const void* __restrict__ idx_raw,
             const float* __restrict__ wgt,
             const float* __restrict__ bias,
             float* __restrict__ out) {
    extern __shared__ char smem[];
    __half* wsm = (__half*)(smem + SMEM_W);

    const int tid = threadIdx.x;
    const int wid = tid >> 5;
    const int lid = tid & 31;
    const int gid = lid >> 2;       // 0..7
    const int tig = lid & 3;        // 0..3
    const int mb  = wid >> 1;       // 0..7 : 32-pixel block
    const int ch  = wid & 1;        // 0..1 : 32-co half
    const int is64 = g_idx_is64;

    // ldmatrix per-lane address constant
    const int lm = lid >> 3, lr = lid & 7;
    const uint32_t lconst = (uint32_t)(((lm & 1) * 8 + lr) * A_PITCH_B
                                       + (lm >> 1) * 16 + mb * 32 * A_PITCH_B);

    // stage weights as fp16: wsm[j][co][ci]
    for (int e = tid; e < C_ * C_ * 9; e += THREADS) {
        int ci = e & 63, co = (e >> 6) & 63, j = e >> 12;
        wsm[j * W_TAP_H + co * W_ROW_H + ci] =
            __float2half_rn(wgt[co * 576 + ci * 9 + j]);
    }

    // per-thread bias registers
    float br[4][2];
#pragma unroll
    for (int nt = 0; nt < 4; ++nt) {
        int co = ch * 32 + nt * 8 + 2 * tig;
        br[nt][0] = bias[co];
        br[nt][1] = bias[co + 1];
    }

    const uint32_t barb   = smem_u32(smem + SMEM_BAR);
    const uint32_t abase0 = smem_u32(smem + SMEM_A);
    if (tid == 0) {
        MBARRIER_INIT(barb + 0, 1);
        MBARRIER_INIT(barb + 8, 1);
        MBARRIER_INIT(barb + 16, 1);
    }
    __syncthreads();

    const int nloc = (N_TILES - (int)blockIdx.x + (int)gridDim.x - 1) / (int)gridDim.x;
    const int S = nloc * 9;
    if (S == 0) return;

    // prologue: fill stages 0 and 1
    Cur c_iss = {(int)blockIdx.x, 0};
    {
        if (tid == 0) MBARRIER_EXPECT_TX(barb + 0, A_FILL_B);
        __syncthreads();
        if (tid < TILE_P) {
            int g = load_idx(idx_raw, is64, c_iss, tid);
            issue_row(c_iss.tile, g, tid, abase0, barb + 0);
        }
        adv(c_iss, gridDim.x);
        if (S > 1) {
            if (tid == 0) MBARRIER_EXPECT_TX(barb + 8, A_FILL_B);
            __syncthreads();
            if (tid < TILE_P) {
                int g = load_idx(idx_raw, is64, c_iss, tid);
                issue_row(c_iss.tile, g, tid, abase0 + A_BYTES, barb + 8);
            }
            adv(c_iss, gridDim.x);
        }
    }
    Cur c_pre = c_iss;                 // idx prefetch cursor (for c_iss's step)
    int r_use = 0;
    if (S > 2 && tid < TILE_P) r_use = load_idx(idx_raw, is64, c_pre, tid);
    adv(c_pre, gridDim.x);

    Cur c_cmp = {(int)blockIdx.x, 0};
    int b_iss = 2, b_cmp = 0;
    int phase[3] = {0, 0, 0};

    float acc[2][4][4];

    for (int s = 0; s < S; ++s) {
        // wait current compute stage data
        MBARRIER_WAIT_PARITY(barb + 8 * b_cmp, phase[b_cmp]);
        phase[b_cmp] ^= 1;
        __syncthreads();   // all warps done with stage b_iss's previous compute

        if (s + 2 < S && tid == 0)
            MBARRIER_EXPECT_TX(barb + 8 * b_iss, A_FILL_B);
        __syncthreads();
        if (s + 2 < S && tid < TILE_P)
            issue_row(c_iss.tile, r_use, tid, abase0 + b_iss * A_BYTES, barb + 8 * b_iss);
        if (s + 3 < S && tid < TILE_P)
            r_use = load_idx(idx_raw, is64, c_pre, tid);
        adv(c_iss, gridDim.x);
        adv(c_pre, gridDim.x);
        if (++b_iss == 3) b_iss = 0;

        if (c_cmp.tap == 0) {
#pragma unroll
            for (int mh = 0; mh < 2; ++mh)
#pragma unroll
                for (int nt = 0; nt < 4; ++nt)
#pragma unroll
                    for (int q = 0; q < 4; ++q) acc[mh][nt][q] = 0.f;
        }

        // compute tap c_cmp.tap from ring stage b_cmp
        {
            const uint32_t ab = abase0 + b_cmp * A_BYTES;
            const __half* wt = wsm + c_cmp.tap * W_TAP_H
                             + (ch * 32 + gid) * W_ROW_H + tig * 2;
#pragma unroll
            for (int ks = 0; ks < 4; ++ks) {
                uint32_t a[2][4];
#pragma unroll
                for (int mh = 0; mh < 2; ++mh)
                    ldmatrix_x4(a[mh], ab + lconst + mh * (16 * A_PITCH_B) + ks * 32);
#pragma unroll
                for (int nt = 0; nt < 4; ++nt) {
                    const __half* wp = wt + nt * 8 * W_ROW_H + ks * 16;
                    uint32_t b0 = *(const uint32_t*)(wp);
                    uint32_t b1 = *(const uint32_t*)(wp + 8);
                    mma_f16(acc[0][nt], a[0], b0, b1);
                    mma_f16(acc[1][nt], a[1], b0, b1);
                }
            }
        }

        if (c_cmp.tap == 8) {
            // epilogue: direct STG from accumulators
            int b  = c_cmp.tile >> 9;
            int pt = c_cmp.tile & (TILES_PER_B - 1);
            int hw0 = (pt >> 1) * W_ + ((pt & 1) << 8);
            float* op = out + ((size_t)b << 23) + hw0;
#pragma unroll
            for (int mh = 0; mh < 2; ++mh) {
                int px = mb * 32 + mh * 16 + gid;
#pragma unroll
                for (int nt = 0; nt < 4; ++nt) {
                    int co = ch * 32 + nt * 8 + 2 * tig;
                    float* q = op + (size_t)co * HW + px;
                    q[0]      = acc[mh][nt][0] + br[nt][0];
                    q[HW]     = acc[mh][nt][1] + br[nt][1];
                    q[8]      = acc[mh][nt][2] + br[nt][0];
                    q[HW + 8] = acc[mh][nt][3] + br[nt][1];
                }
            }
        }

        adv(c_cmp, gridDim.x);
        if (++b_cmp == 3) b_cmp = 0;
    }
}

// ---------------------------------------------------------------------------
// Launch
// ---------------------------------------------------------------------------
extern "C" void kernel_launch(void* const* d_in, const int* in_sizes, int n_in,
                              void* d_out, int out_size) {
    const float* x    = (const float*)d_in[0];
    const void*  idx  = d_in[1];
    const float* wgt  = (const float*)d_in[2];
    const float* bias = (const float*)d_in[3];
    float* out        = (float*)d_out;

    detect_kernel<<<1, 32>>>((const unsigned int*)idx);

    dim3 tb(32, 8);
    dim3 tg(HW / 32, C_ / 32, B_);
    transpose_kernel<<<tg, tb>>>(x);

    cudaFuncSetAttribute(latconv_main, cudaFuncAttributeMaxDynamicSharedMemorySize,
                         SMEM_TOTAL);
    int sm_count = 0;
    cudaDeviceGetAttribute(&sm_count, cudaDevAttrMultiProcessorCount, 0);
    if (sm_count <= 0) sm_count = 148;

    latconv_main<<<sm_count, THREADS, SMEM_TOTAL>>>(idx, wgt, bias, out);
}

// round 8
// speedup vs baseline: 2.2486x; 1.1253x over previous
#include <cuda_runtime.h>
#include <cuda_fp16.h>
#include <cstdint>

// ---------------------------------------------------------------------------
// Problem constants
// ---------------------------------------------------------------------------
static constexpr int B_  = 4;
static constexpr int C_  = 64;
static constexpr int H_  = 256;
static constexpr int W_  = 512;
static constexpr int HW  = H_ * W_;               // 131072 = 2^17
static constexpr int SW_ = 3 * W_;                // 1536
static constexpr int TILE_P = 512;                // one full image row
static constexpr int TILES_PER_B = HW / TILE_P;   // 256
static constexpr int N_TILES = B_ * TILES_PER_B;  // 1024
static constexpr int THREADS = 512;               // 16 warps

// A stages: 512 px rows x 144B pitch (128B data + 16B pad, ldmatrix-friendly)
static constexpr int A_PITCH_B = 144;
static constexpr int A_BYTES   = TILE_P * A_PITCH_B;        // 73728
// W: [tap][co][ci] halves, 128B rows, chunk-XOR swizzled (conflict-free LDS)
static constexpr int W_TAP_B   = C_ * 128;                  // 8192
static constexpr int W_BYTES   = 9 * W_TAP_B;               // 73728

static constexpr int SMEM_W    = 0;
static constexpr int SMEM_BIAS = W_BYTES;                   // 256 B
static constexpr int SMEM_BAR  = W_BYTES + 256;             // 4 x 8B mbarriers
static constexpr int SMEM_A    = W_BYTES + 512;             // 74240 (128-aligned)
static constexpr int SMEM_TOTAL = SMEM_A + 2 * A_BYTES;     // 221696

__device__ int    g_idx_is64;
__device__ __align__(128) __half g_xt[(size_t)B_ * HW * C_];  // [B][HW][C] fp16

// ---------------------------------------------------------------------------
// PTX helpers
// ---------------------------------------------------------------------------
__device__ __forceinline__ uint32_t smem_u32(const void* p) {
    uint32_t a;
    asm("{ .reg .u64 t; cvta.to.shared.u64 t, %1; cvt.u32.u64 %0, t; }" : "=r"(a) : "l"(p));
    return a;
}

__device__ __forceinline__ void ldmatrix_x4(uint32_t* r, uint32_t addr) {
    asm volatile("ldmatrix.sync.aligned.m8n8.x4.shared.b16 {%0,%1,%2,%3}, [%4];"
                 : "=r"(r[0]), "=r"(r[1]), "=r"(r[2]), "=r"(r[3]) : "r"(addr));
}

__device__ __forceinline__ void mma_f16(float* c, const uint32_t* a, uint32_t b0, uint32_t b1) {
    asm volatile(
        "mma.sync.aligned.m16n8k16.row.col.f32.f16.f16.f32 "
        "{%0,%1,%2,%3}, {%4,%5,%6,%7}, {%8,%9}, {%0,%1,%2,%3};"
        : "+f"(c[0]), "+f"(c[1]), "+f"(c[2]), "+f"(c[3])
        : "r"(a[0]), "r"(a[1]), "r"(a[2]), "r"(a[3]), "r"(b0), "r"(b1));
}

#define MBARRIER_INIT(bar, cnt) \
    asm volatile("mbarrier.init.shared.b64 [%0], %1;" :: "r"(bar), "r"((uint32_t)(cnt)) : "memory")

// fused arrive + expect-tx (per issuing thread)
#define MBARRIER_EXPECT_TX(bar, bytes) \
    asm volatile("mbarrier.arrive.expect_tx.shared.b64 _, [%0], %1;" \
                 :: "r"(bar), "r"((uint32_t)(bytes)) : "memory")

#define MBARRIER_WAIT_PARITY(bar, ph) do {                                              \
    uint32_t _m = (bar); uint32_t _p = (ph); uint32_t _d;                               \
    asm volatile("{\n\t.reg .pred p;\n\t"                                               \
        "mbarrier.try_wait.parity.acquire.cta.shared::cta.b64 p, [%1], %2;\n\t"         \
        "selp.b32 %0, 1, 0, p;\n\t}" : "=r"(_d) : "r"(_m), "r"(_p) : "memory");         \
    if (!_d) {                                                                          \
        asm volatile("{\n\t.reg .pred P1;\n\t"                                          \
            "WL_%=:\n\t"                                                                \
            "mbarrier.try_wait.parity.acquire.cta.shared::cta.b64 P1, [%0], %1, 0x989680;\n\t" \
            "@P1 bra.uni WD_%=;\n\t"                                                    \
            "bra.uni WL_%=;\n\t"                                                        \
            "WD_%=:\n\t}" :: "r"(_m), "r"(_p) : "memory");                              \
    }                                                                                   \
} while (0)

// one 128-byte row: global -> shared, completion counted on mbar
__device__ __forceinline__ void bulk_row(uint32_t dst, const void* src, uint32_t mbar) {
    asm volatile(
        "cp.async.bulk.shared::cta.global.mbarrier::complete_tx::bytes [%0], [%1], 128, [%2];"
        :: "r"(dst), "l"(src), "r"(mbar) : "memory");
}

// ---------------------------------------------------------------------------
// Kernel 0: idx dtype detect
// ---------------------------------------------------------------------------
__global__ void detect_kernel(const unsigned int* __restrict__ w) {
    if (threadIdx.x == 0) {
        int is64 = 1;
        for (int i = 0; i < 64; ++i)
            if (w[2 * i + 1] != 0u) { is64 = 0; break; }
        g_idx_is64 = is64;
    }
}

// ---------------------------------------------------------------------------
// Kernel 1: transpose x [B][C][HW] -> g_xt [B][HW][C] fp16 (coalesced stores)
// ---------------------------------------------------------------------------
__global__ void transpose_kernel(const float* __restrict__ x) {
    __shared__ float t[32][33];
    const int b  = blockIdx.z;
    const int cb = blockIdx.y * 32;
    const int gb = blockIdx.x * 32;
    const int tx = threadIdx.x, ty = threadIdx.y;
    const float* xb = x + (size_t)b * C_ * HW;
#pragma unroll
    for (int i = 0; i < 32; i += 8)
        t[ty + i][tx] = xb[(size_t)(cb + ty + i) * HW + gb + tx];
    __syncthreads();
    __half* xtb = g_xt + ((size_t)b * HW) * C_;
    const int c2  = tx & 15;
    const int sel = tx >> 4;
#pragma unroll
    for (int i = 0; i < 2; ++i) {
        int hwl = ty * 4 + sel * 2 + i;
        __half2 v = __floats2half2_rn(t[2 * c2][hwl], t[2 * c2 + 1][hwl]);
        *(__half2*)(xtb + (size_t)(gb + hwl) * C_ + cb + 2 * c2) = v;
    }
}

// ---------------------------------------------------------------------------
// Kernel 2: persistent fused gather (cp.async.bulk, 2-stage x half-split
//           mbarrier ring) + fp16 mma.sync.  tile = 512 px x 64 co.
//           16 warps: warp w computes px [w*32, w*32+32) x all 64 co.
// ---------------------------------------------------------------------------
struct Cur { int tile; int tap; };
__device__ __forceinline__ void adv(Cur& c, int stride) {
    if (++c.tap == 9) { c.tap = 0; c.tile += stride; }
}

__device__ __forceinline__ int load_idx(const void* idx, int is64, const Cur& c, int p) {
    int pt = c.tile & (TILES_PER_B - 1);       // image row
    int kh = c.tap / 3;
    int kw = c.tap - kh * 3;
    int o  = (3 * pt + kh) * SW_ + 3 * p + kw;
    return is64 ? (int)((const long long*)idx)[o] : ((const int*)idx)[o];
}

__device__ __forceinline__ void issue_row(int tile, int g, int p,
                                          uint32_t stage_base, uint32_t mbar) {
    const char* src = (const char*)g_xt
                    + ((((size_t)(tile >> 8)) << 17) + (uint32_t)g) * (C_ * 2);
    bulk_row(stage_base + p * A_PITCH_B, src, mbar);
}

__global__ void __launch_bounds__(THREADS, 1)
latconv_main(const void* __restrict__ idx_raw,
             const float* __restrict__ wgt,
             const float* __restrict__ bias,
             float* __restrict__ out) {
    extern __shared__ char smem[];
    const uint32_t wbase = smem_u32(smem + SMEM_W);
    float* bsm = (float*)(smem + SMEM_BIAS);

    const int tid = threadIdx.x;
    const int wid = tid >> 5;
    const int lid = tid & 31;
    const int gid = lid >> 2;       // 0..7
    const int tig = lid & 3;        // 0..3
    const int is64 = g_idx_is64;

    // ldmatrix per-lane address constant (16x16 A tiles, 144B pitch)
    const int lm = lid >> 3, lr = lid & 7;
    const uint32_t lconst = (uint32_t)(((lm & 1) * 8 + lr) * A_PITCH_B
                                       + (lm >> 1) * 16 + wid * 32 * A_PITCH_B);

    // stage weights fp16, chunk-XOR swizzle: byte(j,co,ci) =
    //   j*8192 + co*128 + ((ci>>3)^(co&7))*16 + (ci&7)*2
    for (int e = tid; e < C_ * C_ * 9; e += THREADS) {
        int ci = e & 63, co = (e >> 6) & 63, j = e >> 12;
        uint32_t off = (uint32_t)(j * W_TAP_B + co * 128
                     + (((ci >> 3) ^ (co & 7)) << 4) + ((ci & 7) << 1));
        *(__half*)(smem + SMEM_W + off) = __float2half_rn(wgt[co * 576 + ci * 9 + j]);
    }
    if (tid < C_) bsm[tid] = bias[tid];

    const uint32_t barb   = smem_u32(smem + SMEM_BAR);
    const uint32_t abase0 = smem_u32(smem + SMEM_A);
    if (tid == 0) {
#pragma unroll
        for (int i = 0; i < 4; ++i) MBARRIER_INIT(barb + 8 * i, 256);
    }
    __syncthreads();

    const int nloc = (N_TILES - (int)blockIdx.x + (int)gridDim.x - 1) / (int)gridDim.x;
    const int S = nloc * 9;
    if (S == 0) return;

    const int half = tid >> 8;                 // gather half (0/1)
    const int whalf = wid >> 3;                // compute-wait half (0/1)

    // prologue: fill stage 0
    Cur c0 = {(int)blockIdx.x, 0};
    {
        int g = load_idx(idx_raw, is64, c0, tid);
        MBARRIER_EXPECT_TX(barb + half * 8, 128);
        issue_row(c0.tile, g, tid, abase0, barb + half * 8);
    }
    Cur c_iss = c0; adv(c_iss, gridDim.x);     // step 1
    int r_use = (S > 1) ? load_idx(idx_raw, is64, c_iss, tid) : 0;
    Cur c_pre = c_iss; adv(c_pre, gridDim.x);  // step 2

    Cur c_cmp = {(int)blockIdx.x, 0};
    int ph[2] = {0, 0};

    float acc[2][8][4];

    for (int s = 0; s < S; ++s) {
        __syncthreads();   // all warps finished step s-1 -> stage (s+1)&1 free

        if (s + 1 < S) {
            const int bi = (s + 1) & 1;
            MBARRIER_EXPECT_TX(barb + bi * 16 + half * 8, 128);
            issue_row(c_iss.tile, r_use, tid, abase0 + bi * A_BYTES,
                      barb + bi * 16 + half * 8);
        }
        if (s + 2 < S) r_use = load_idx(idx_raw, is64, c_pre, tid);
        adv(c_iss, gridDim.x);
        adv(c_pre, gridDim.x);

        if (c_cmp.tap == 0) {
#pragma unroll
            for (int mh = 0; mh < 2; ++mh)
#pragma unroll
                for (int nt = 0; nt < 8; ++nt)
#pragma unroll
                    for (int q = 0; q < 4; ++q) acc[mh][nt][q] = 0.f;
        }

        // wait my half of current stage, then compute tap
        const int bc = s & 1;
        MBARRIER_WAIT_PARITY(barb + bc * 16 + whalf * 8, ph[bc]);
        ph[bc] ^= 1;

        {
            const uint32_t ab = abase0 + bc * A_BYTES;
            // per-thread W base: co = gid within each nt-block of 8
            const uint32_t wb = wbase + (uint32_t)c_cmp.tap * W_TAP_B
                              + (uint32_t)gid * 128 + (uint32_t)tig * 4;
#pragma unroll
            for (int ks = 0; ks < 4; ++ks) {
                uint32_t a[2][4];
#pragma unroll
                for (int mh = 0; mh < 2; ++mh)
                    ldmatrix_x4(a[mh], ab + lconst + mh * (16 * A_PITCH_B) + ks * 32);
                const uint32_t c0off = (uint32_t)(((2 * ks)     ^ gid) << 4);
                const uint32_t c1off = (uint32_t)(((2 * ks + 1) ^ gid) << 4);
#pragma unroll
                for (int nt = 0; nt < 8; ++nt) {
                    uint32_t wrow = wb + nt * 1024;
                    uint32_t b0, b1;
                    asm volatile("ld.shared.b32 %0, [%1];" : "=r"(b0) : "r"(wrow + c0off));
                    asm volatile("ld.shared.b32 %0, [%1];" : "=r"(b1) : "r"(wrow + c1off));
                    mma_f16(acc[0][nt], a[0], b0, b1);
                    mma_f16(acc[1][nt], a[1], b0, b1);
                }
            }
        }

        if (c_cmp.tap == 8) {
            // epilogue: direct STG from accumulators
            int b  = c_cmp.tile >> 8;
            int pt = c_cmp.tile & (TILES_PER_B - 1);
            float* op = out + ((size_t)b << 23) + (size_t)pt * TILE_P;
#pragma unroll
            for (int mh = 0; mh < 2; ++mh) {
                int px = wid * 32 + mh * 16 + gid;
#pragma unroll
                for (int nt = 0; nt < 8; ++nt) {
                    int co = nt * 8 + 2 * tig;
                    float b0 = bsm[co], b1 = bsm[co + 1];
                    float* q = op + (size_t)co * HW + px;
                    q[0]      = acc[mh][nt][0] + b0;
                    q[HW]     = acc[mh][nt][1] + b1;
                    q[8]      = acc[mh][nt][2] + b0;
                    q[HW + 8] = acc[mh][nt][3] + b1;
                }
            }
        }

        adv(c_cmp, gridDim.x);
    }
}

// ---------------------------------------------------------------------------
// Launch
// ---------------------------------------------------------------------------
extern "C" void kernel_launch(void* const* d_in, const int* in_sizes, int n_in,
                              void* d_out, int out_size) {
    const float* x    = (const float*)d_in[0];
    const void*  idx  = d_in[1];
    const float* wgt  = (const float*)d_in[2];
    const float* bias = (const float*)d_in[3];
    float* out        = (float*)d_out;

    detect_kernel<<<1, 32>>>((const unsigned int*)idx);

    dim3 tb(32, 8);
    dim3 tg(HW / 32, C_ / 32, B_);
    transpose_kernel<<<tg, tb>>>(x);

    cudaFuncSetAttribute(latconv_main, cudaFuncAttributeMaxDynamicSharedMemorySize,
                         SMEM_TOTAL);
    int sm_count = 0;
    cudaDeviceGetAttribute(&sm_count, cudaDevAttrMultiProcessorCount, 0);
    if (sm_count <= 0) sm_count = 148;

    latconv_main<<<sm_count, THREADS, SMEM_TOTAL>>>(idx, wgt, bias, out);
}